// round 7
// baseline (speedup 1.0000x reference)
#include <cuda_runtime.h>

#define N_NODES 100000
#define E_EDGES 1600000
#define HDIM 48
#define NQ (HDIM / 4)   // 12 float4 columns
#define CAP 96          // max tracked in-degree (Poisson(16): P(>50) ~ 1e-11)

#define TM 128          // node tile per block
#define SXS 132         // padded shared tile stride (128 + 4)
#define THR 384         // 32 M-tiles x 12 N-tiles, micro-tile 4M x 4N

// Persistent scratch (no allocations allowed).
__device__ float g_h[N_NODES * HDIM];        // current node features
__device__ float g_agg[N_NODES * HDIM];      // self + neighbor sum (MLP input)
__device__ int   g_count[N_NODES];           // in-degree counters
__device__ int   g_slots[N_NODES * CAP];     // per-dst source lists

// ---------------------------------------------------------------------------
// init: h = x ; count = 0
// ---------------------------------------------------------------------------
__global__ void init_kernel(const float* __restrict__ x) {
    int i = blockIdx.x * blockDim.x + threadIdx.x;
    if (i < N_NODES * NQ) ((float4*)g_h)[i] = ((const float4*)x)[i];
    if (i < N_NODES) g_count[i] = 0;
}

// ---------------------------------------------------------------------------
// build adjacency: bin src indices by dst. 4 edges per thread (int4 loads,
// batched atomics -> MLP=4 instead of 1).
// ---------------------------------------------------------------------------
__global__ void build_kernel(const int* __restrict__ ei) {
    int t = blockIdx.x * blockDim.x + threadIdx.x;
    int e0 = t * 4;
    if (e0 >= E_EDGES) return;
    int4 src4 = *(const int4*)(ei + e0);
    int4 dst4 = *(const int4*)(ei + E_EDGES + e0);
    int p0 = atomicAdd(&g_count[dst4.x], 1);
    int p1 = atomicAdd(&g_count[dst4.y], 1);
    int p2 = atomicAdd(&g_count[dst4.z], 1);
    int p3 = atomicAdd(&g_count[dst4.w], 1);
    if (p0 < CAP) g_slots[dst4.x * CAP + p0] = src4.x;
    if (p1 < CAP) g_slots[dst4.y * CAP + p1] = src4.y;
    if (p2 < CAP) g_slots[dst4.z * CAP + p2] = src4.z;
    if (p3 < CAP) g_slots[dst4.w * CAP + p3] = src4.w;
}

// ---------------------------------------------------------------------------
// gather: agg[n] = h[n] + sum_{s in adj(n)} h[s]
// One thread per (node, float4 col): 300k threads, high occupancy, many
// outstanding L2 loads. At the LTS roofline (~27us).
// ---------------------------------------------------------------------------
__global__ void gather_kernel() {
    int idx = blockIdx.x * blockDim.x + threadIdx.x;
    if (idx >= N_NODES * NQ) return;
    int n = idx / NQ;
    int c = idx % NQ;

    const float4* __restrict__ h4 = (const float4*)g_h;
    float4 acc = h4[n * NQ + c];                        // self (eps=0 GIN)
    int deg = min(g_count[n], CAP);
    const int* __restrict__ sl = g_slots + n * CAP;

    int i = 0;
    for (; i + 4 <= deg; i += 4) {
        int s0 = sl[i], s1 = sl[i + 1], s2 = sl[i + 2], s3 = sl[i + 3];
        float4 v0 = h4[s0 * NQ + c];
        float4 v1 = h4[s1 * NQ + c];
        float4 v2 = h4[s2 * NQ + c];
        float4 v3 = h4[s3 * NQ + c];
        acc.x += (v0.x + v1.x) + (v2.x + v3.x);
        acc.y += (v0.y + v1.y) + (v2.y + v3.y);
        acc.z += (v0.z + v1.z) + (v2.z + v3.z);
        acc.w += (v0.w + v1.w) + (v2.w + v3.w);
    }
    for (; i < deg; i++) {
        int s = sl[i];
        float4 v = h4[s * NQ + c];
        acc.x += v.x; acc.y += v.y; acc.z += v.z; acc.w += v.w;
    }
    ((float4*)g_agg)[n * NQ + c] = acc;
}

// ---------------------------------------------------------------------------
// 48->48 layer, result back into sT. 384 threads: thread (mt=tid/12 in 0..31,
// nt=tid%12) computes a 4M x 4N micro-tile: per k-iter just
// 1 LDS.128 + 1 LDG.128 + 16 FFMA (89% FFMA mix), low reg pressure.
// ---------------------------------------------------------------------------
__device__ __forceinline__ void layer48_to_smem(
    float* sT, const float* __restrict__ W, const float* __restrict__ B,
    int tid, bool relu) {
    int mt = tid / 12, nt = tid % 12;
    int m0 = mt * 4;
    const float4* __restrict__ W4 = (const float4*)W;
    float4 bias = ((const float4*)B)[nt];

    float acc[4][4];
#pragma unroll
    for (int m = 0; m < 4; m++) {
        acc[m][0] = bias.x; acc[m][1] = bias.y;
        acc[m][2] = bias.z; acc[m][3] = bias.w;
    }
#pragma unroll 4
    for (int k = 0; k < HDIM; k++) {
        float4 b4 = W4[k * NQ + nt];
        float4 a4 = *(const float4*)&sT[k * SXS + m0];
        float a[4] = {a4.x, a4.y, a4.z, a4.w};
#pragma unroll
        for (int m = 0; m < 4; m++) {
            acc[m][0] += a[m] * b4.x;
            acc[m][1] += a[m] * b4.y;
            acc[m][2] += a[m] * b4.z;
            acc[m][3] += a[m] * b4.w;
        }
    }
    __syncthreads();   // all reads of sT complete before overwriting
#pragma unroll
    for (int n = 0; n < 4; n++) {
        float4 v = make_float4(acc[0][n], acc[1][n], acc[2][n], acc[3][n]);
        if (relu) {
            v.x = fmaxf(v.x, 0.f); v.y = fmaxf(v.y, 0.f);
            v.z = fmaxf(v.z, 0.f); v.w = fmaxf(v.w, 0.f);
        }
        *(float4*)&sT[(nt * 4 + n) * SXS + m0] = v;
    }
    __syncthreads();
}

// 48 -> 48 layer writing straight to global gout[node*48 + f] (with relu).
__device__ __forceinline__ void layer48_to_gmem(
    const float* sT, const float* __restrict__ W, const float* __restrict__ B,
    int tid, int base, float* __restrict__ gout, bool relu) {
    int mt = tid / 12, nt = tid % 12;
    int m0 = mt * 4;
    const float4* __restrict__ W4 = (const float4*)W;
    float4 bias = ((const float4*)B)[nt];

    float acc[4][4];
#pragma unroll
    for (int m = 0; m < 4; m++) {
        acc[m][0] = bias.x; acc[m][1] = bias.y;
        acc[m][2] = bias.z; acc[m][3] = bias.w;
    }
#pragma unroll 4
    for (int k = 0; k < HDIM; k++) {
        float4 b4 = W4[k * NQ + nt];
        float4 a4 = *(const float4*)&sT[k * SXS + m0];
        float a[4] = {a4.x, a4.y, a4.z, a4.w};
#pragma unroll
        for (int m = 0; m < 4; m++) {
            acc[m][0] += a[m] * b4.x;
            acc[m][1] += a[m] * b4.y;
            acc[m][2] += a[m] * b4.z;
            acc[m][3] += a[m] * b4.w;
        }
    }
#pragma unroll
    for (int m = 0; m < 4; m++) {
        int node = base + m0 + m;
        if (node < N_NODES) {
            float4 v = make_float4(acc[m][0], acc[m][1], acc[m][2], acc[m][3]);
            if (relu) {
                v.x = fmaxf(v.x, 0.f); v.y = fmaxf(v.y, 0.f);
                v.z = fmaxf(v.z, 0.f); v.w = fmaxf(v.w, 0.f);
            }
            *(float4*)&gout[node * HDIM + nt * 4] = v;
        }
    }
}

// 48 -> 16 layer writing to global out[node*16 + f] (no relu). 128 active thr.
__device__ __forceinline__ void layer16_to_gmem(
    const float* sT, const float* __restrict__ W, const float* __restrict__ B,
    int tid, int base, float* __restrict__ out) {
    int mt = tid / 4, nt = tid % 4;
    if (mt >= 32) return;                    // no barriers below this point
    int m0 = mt * 4;
    const float4* __restrict__ W4 = (const float4*)W;   // [48][4 float4 cols]
    float4 bias = ((const float4*)B)[nt];

    float acc[4][4];
#pragma unroll
    for (int m = 0; m < 4; m++) {
        acc[m][0] = bias.x; acc[m][1] = bias.y;
        acc[m][2] = bias.z; acc[m][3] = bias.w;
    }
#pragma unroll 4
    for (int k = 0; k < HDIM; k++) {
        float4 b4 = W4[k * 4 + nt];
        float4 a4 = *(const float4*)&sT[k * SXS + m0];
        float a[4] = {a4.x, a4.y, a4.z, a4.w};
#pragma unroll
        for (int m = 0; m < 4; m++) {
            acc[m][0] += a[m] * b4.x;
            acc[m][1] += a[m] * b4.y;
            acc[m][2] += a[m] * b4.z;
            acc[m][3] += a[m] * b4.w;
        }
    }
#pragma unroll
    for (int m = 0; m < 4; m++) {
        int node = base + m0 + m;
        if (node < N_NODES) {
            float4 v = make_float4(acc[m][0], acc[m][1], acc[m][2], acc[m][3]);
            *(float4*)&out[node * 16 + nt * 4] = v;
        }
    }
}

// Load 128-node tile of g_agg into sT transposed ([feat][node]).
__device__ __forceinline__ void load_tile(float* sT, int tid, int base) {
    const float4* __restrict__ in4 = (const float4*)g_agg;
    for (int i = tid; i < TM * NQ; i += THR) {
        int m = i % TM;          // consecutive threads -> consecutive columns
        int c = i / TM;
        int node = base + m;
        float4 v = make_float4(0.f, 0.f, 0.f, 0.f);
        if (node < N_NODES) v = in4[node * NQ + c];
        sT[(4 * c + 0) * SXS + m] = v.x;
        sT[(4 * c + 1) * SXS + m] = v.y;
        sT[(4 * c + 2) * SXS + m] = v.z;
        sT[(4 * c + 3) * SXS + m] = v.w;
    }
    __syncthreads();
}

// ---------------------------------------------------------------------------
// Conv MLP: g_agg -> relu(.W1+b1) -> relu(.W2+b2) -> g_h
// ---------------------------------------------------------------------------
__global__ __launch_bounds__(THR, 4) void conv_mlp_kernel(
    const float* __restrict__ W1, const float* __restrict__ b1,
    const float* __restrict__ W2, const float* __restrict__ b2) {
    __shared__ float sT[HDIM * SXS];
    int tid = threadIdx.x;
    int base = blockIdx.x * TM;
    load_tile(sT, tid, base);
    layer48_to_smem(sT, W1, b1, tid, true);
    layer48_to_gmem(sT, W2, b2, tid, base, g_h, true);
}

// ---------------------------------------------------------------------------
// Final fused kernel: conv3 MLP + fc head (4 layers), writes d_out.
// ---------------------------------------------------------------------------
__global__ __launch_bounds__(THR, 4) void final_mlp_kernel(
    const float* __restrict__ W1, const float* __restrict__ b1,
    const float* __restrict__ W2, const float* __restrict__ b2,
    const float* __restrict__ W3, const float* __restrict__ b3,
    const float* __restrict__ W4, const float* __restrict__ b4,
    float* __restrict__ out) {
    __shared__ float sT[HDIM * SXS];
    int tid = threadIdx.x;
    int base = blockIdx.x * TM;
    load_tile(sT, tid, base);
    layer48_to_smem(sT, W1, b1, tid, true);   // conv3 layer 1
    layer48_to_smem(sT, W2, b2, tid, true);   // conv3 layer 2
    layer48_to_smem(sT, W3, b3, tid, true);   // fc1 + relu
    layer16_to_gmem(sT, W4, b4, tid, base, out);  // fc2 -> out
}

// ---------------------------------------------------------------------------
extern "C" void kernel_launch(void* const* d_in, const int* in_sizes, int n_in,
                              void* d_out, int out_size) {
    const float* x   = (const float*)d_in[0];
    const int*   ei  = (const int*)d_in[1];
    const float* w11 = (const float*)d_in[2];
    const float* b11 = (const float*)d_in[3];
    const float* w12 = (const float*)d_in[4];
    const float* b12 = (const float*)d_in[5];
    const float* w21 = (const float*)d_in[6];
    const float* b21 = (const float*)d_in[7];
    const float* w22 = (const float*)d_in[8];
    const float* b22 = (const float*)d_in[9];
    const float* w31 = (const float*)d_in[10];
    const float* b31 = (const float*)d_in[11];
    const float* w32 = (const float*)d_in[12];
    const float* b32 = (const float*)d_in[13];
    const float* wf1 = (const float*)d_in[14];
    const float* bf1 = (const float*)d_in[15];
    const float* wf2 = (const float*)d_in[16];
    const float* bf2 = (const float*)d_in[17];
    float* out = (float*)d_out;

    const int TPB = 256;
    const int init_grid   = (N_NODES * NQ + TPB - 1) / TPB;
    const int build_grid  = (E_EDGES / 4 + TPB - 1) / TPB;
    const int gather_grid = (N_NODES * NQ + TPB - 1) / TPB;
    const int mlp_grid    = (N_NODES + TM - 1) / TM;

    init_kernel<<<init_grid, TPB>>>(x);
    build_kernel<<<build_grid, TPB>>>(ei);   // adjacency built ONCE, reused x3

    // Conv 1
    gather_kernel<<<gather_grid, TPB>>>();
    conv_mlp_kernel<<<mlp_grid, THR>>>(w11, b11, w12, b12);
    // Conv 2
    gather_kernel<<<gather_grid, TPB>>>();
    conv_mlp_kernel<<<mlp_grid, THR>>>(w21, b21, w22, b22);
    // Conv 3 + head fused
    gather_kernel<<<gather_grid, TPB>>>();
    final_mlp_kernel<<<mlp_grid, THR>>>(w31, b31, w32, b32,
                                        wf1, bf1, wf2, bf2, out);

    (void)in_sizes; (void)n_in; (void)out_size;
}

// round 8
// speedup vs baseline: 1.2054x; 1.2054x over previous
#include <cuda_runtime.h>

#define N_NODES 100000
#define E_EDGES 1600000
#define HDIM 48
#define NQ (HDIM / 4)   // 12 float4 columns
#define CAP 96          // max tracked in-degree (Poisson(16): P(>50) ~ 1e-11)

#define TM 256          // node tile per block -> grid 391 = ONE wave @3 blk/SM
#define SXS 256         // shared tile stride (48*256*4 = 48KB exactly)
#define THR 384         // 32 M-tiles (8 nodes each) x 12 N-tiles

// Persistent scratch (no allocations allowed).
__device__ float g_h[N_NODES * HDIM];        // current node features
__device__ float g_agg[N_NODES * HDIM];      // self + neighbor sum (MLP input)
__device__ int   g_count[N_NODES];           // in-degree counters
__device__ int   g_slots[N_NODES * CAP];     // per-dst source lists

// ---------------------------------------------------------------------------
// init: h = x ; count = 0
// ---------------------------------------------------------------------------
__global__ void init_kernel(const float* __restrict__ x) {
    int i = blockIdx.x * blockDim.x + threadIdx.x;
    if (i < N_NODES * NQ) ((float4*)g_h)[i] = ((const float4*)x)[i];
    if (i < N_NODES) g_count[i] = 0;
}

// ---------------------------------------------------------------------------
// build adjacency: bin src indices by dst. 4 edges per thread (int4 loads,
// batched atomics -> MLP=4).
// ---------------------------------------------------------------------------
__global__ void build_kernel(const int* __restrict__ ei) {
    int t = blockIdx.x * blockDim.x + threadIdx.x;
    int e0 = t * 4;
    if (e0 >= E_EDGES) return;
    int4 src4 = *(const int4*)(ei + e0);
    int4 dst4 = *(const int4*)(ei + E_EDGES + e0);
    int p0 = atomicAdd(&g_count[dst4.x], 1);
    int p1 = atomicAdd(&g_count[dst4.y], 1);
    int p2 = atomicAdd(&g_count[dst4.z], 1);
    int p3 = atomicAdd(&g_count[dst4.w], 1);
    if (p0 < CAP) g_slots[dst4.x * CAP + p0] = src4.x;
    if (p1 < CAP) g_slots[dst4.y * CAP + p1] = src4.y;
    if (p2 < CAP) g_slots[dst4.z * CAP + p2] = src4.z;
    if (p3 < CAP) g_slots[dst4.w * CAP + p3] = src4.w;
}

// ---------------------------------------------------------------------------
// gather: agg[n] = h[n] + sum_{s in adj(n)} h[s]   (at the LTS roofline)
// ---------------------------------------------------------------------------
__global__ void gather_kernel() {
    int idx = blockIdx.x * blockDim.x + threadIdx.x;
    if (idx >= N_NODES * NQ) return;
    int n = idx / NQ;
    int c = idx % NQ;

    const float4* __restrict__ h4 = (const float4*)g_h;
    float4 acc = h4[n * NQ + c];                        // self (eps=0 GIN)
    int deg = min(g_count[n], CAP);
    const int* __restrict__ sl = g_slots + n * CAP;

    int i = 0;
    for (; i + 4 <= deg; i += 4) {
        int s0 = sl[i], s1 = sl[i + 1], s2 = sl[i + 2], s3 = sl[i + 3];
        float4 v0 = h4[s0 * NQ + c];
        float4 v1 = h4[s1 * NQ + c];
        float4 v2 = h4[s2 * NQ + c];
        float4 v3 = h4[s3 * NQ + c];
        acc.x += (v0.x + v1.x) + (v2.x + v3.x);
        acc.y += (v0.y + v1.y) + (v2.y + v3.y);
        acc.z += (v0.z + v1.z) + (v2.z + v3.z);
        acc.w += (v0.w + v1.w) + (v2.w + v3.w);
    }
    for (; i < deg; i++) {
        int s = sl[i];
        float4 v = h4[s * NQ + c];
        acc.x += v.x; acc.y += v.y; acc.z += v.z; acc.w += v.w;
    }
    ((float4*)g_agg)[n * NQ + c] = acc;
}

// ---------------------------------------------------------------------------
// 48->48 layer, result back into sT (sT[feat][node], stride SXS).
// Thread (mt=tid/12, nt=tid%12) computes an 8M x 4N micro-tile:
// 32 FFMA per (2 LDS.128 + 1 LDG.128); FFMA-pipe bound.
// ---------------------------------------------------------------------------
__device__ __forceinline__ void layer48_to_smem(
    float* sT, const float* __restrict__ W, const float* __restrict__ B,
    int tid, bool relu) {
    int mt = tid / 12, nt = tid % 12;
    int m0 = mt * 8;
    const float4* __restrict__ W4 = (const float4*)W;
    float4 bias = ((const float4*)B)[nt];

    float acc[8][4];
#pragma unroll
    for (int m = 0; m < 8; m++) {
        acc[m][0] = bias.x; acc[m][1] = bias.y;
        acc[m][2] = bias.z; acc[m][3] = bias.w;
    }
#pragma unroll 8
    for (int k = 0; k < HDIM; k++) {
        float4 b4 = W4[k * NQ + nt];
        float4 a0 = *(const float4*)&sT[k * SXS + m0];
        float4 a1 = *(const float4*)&sT[k * SXS + m0 + 4];
        float a[8] = {a0.x, a0.y, a0.z, a0.w, a1.x, a1.y, a1.z, a1.w};
#pragma unroll
        for (int m = 0; m < 8; m++) {
            acc[m][0] += a[m] * b4.x;
            acc[m][1] += a[m] * b4.y;
            acc[m][2] += a[m] * b4.z;
            acc[m][3] += a[m] * b4.w;
        }
    }
    __syncthreads();   // all reads of sT complete before overwriting
#pragma unroll
    for (int n = 0; n < 4; n++) {
        float4 lo = make_float4(acc[0][n], acc[1][n], acc[2][n], acc[3][n]);
        float4 hi = make_float4(acc[4][n], acc[5][n], acc[6][n], acc[7][n]);
        if (relu) {
            lo.x = fmaxf(lo.x, 0.f); lo.y = fmaxf(lo.y, 0.f);
            lo.z = fmaxf(lo.z, 0.f); lo.w = fmaxf(lo.w, 0.f);
            hi.x = fmaxf(hi.x, 0.f); hi.y = fmaxf(hi.y, 0.f);
            hi.z = fmaxf(hi.z, 0.f); hi.w = fmaxf(hi.w, 0.f);
        }
        int row = nt * 4 + n;
        *(float4*)&sT[row * SXS + m0]     = lo;
        *(float4*)&sT[row * SXS + m0 + 4] = hi;
    }
    __syncthreads();
}

// 48 -> 48 layer writing straight to global gout[node*48 + f] (with relu).
__device__ __forceinline__ void layer48_to_gmem(
    const float* sT, const float* __restrict__ W, const float* __restrict__ B,
    int tid, int base, float* __restrict__ gout, bool relu) {
    int mt = tid / 12, nt = tid % 12;
    int m0 = mt * 8;
    const float4* __restrict__ W4 = (const float4*)W;
    float4 bias = ((const float4*)B)[nt];

    float acc[8][4];
#pragma unroll
    for (int m = 0; m < 8; m++) {
        acc[m][0] = bias.x; acc[m][1] = bias.y;
        acc[m][2] = bias.z; acc[m][3] = bias.w;
    }
#pragma unroll 8
    for (int k = 0; k < HDIM; k++) {
        float4 b4 = W4[k * NQ + nt];
        float4 a0 = *(const float4*)&sT[k * SXS + m0];
        float4 a1 = *(const float4*)&sT[k * SXS + m0 + 4];
        float a[8] = {a0.x, a0.y, a0.z, a0.w, a1.x, a1.y, a1.z, a1.w};
#pragma unroll
        for (int m = 0; m < 8; m++) {
            acc[m][0] += a[m] * b4.x;
            acc[m][1] += a[m] * b4.y;
            acc[m][2] += a[m] * b4.z;
            acc[m][3] += a[m] * b4.w;
        }
    }
#pragma unroll
    for (int m = 0; m < 8; m++) {
        int node = base + m0 + m;
        if (node < N_NODES) {
            float4 v = make_float4(acc[m][0], acc[m][1], acc[m][2], acc[m][3]);
            if (relu) {
                v.x = fmaxf(v.x, 0.f); v.y = fmaxf(v.y, 0.f);
                v.z = fmaxf(v.z, 0.f); v.w = fmaxf(v.w, 0.f);
            }
            *(float4*)&gout[node * HDIM + nt * 4] = v;
        }
    }
}

// 48 -> 16 layer writing to global out[node*16 + f] (no relu).
// 256 active threads: mt=tid/4 in 0..63 covers 256 nodes, nt=tid%4.
__device__ __forceinline__ void layer16_to_gmem(
    const float* sT, const float* __restrict__ W, const float* __restrict__ B,
    int tid, int base, float* __restrict__ out) {
    int mt = tid / 4, nt = tid % 4;
    if (mt >= 64) return;                    // no barriers below this point
    int m0 = mt * 4;
    const float4* __restrict__ W4 = (const float4*)W;   // [48][4 float4 cols]
    float4 bias = ((const float4*)B)[nt];

    float acc[4][4];
#pragma unroll
    for (int m = 0; m < 4; m++) {
        acc[m][0] = bias.x; acc[m][1] = bias.y;
        acc[m][2] = bias.z; acc[m][3] = bias.w;
    }
#pragma unroll 8
    for (int k = 0; k < HDIM; k++) {
        float4 b4 = W4[k * 4 + nt];
        float4 a4 = *(const float4*)&sT[k * SXS + m0];
        float a[4] = {a4.x, a4.y, a4.z, a4.w};
#pragma unroll
        for (int m = 0; m < 4; m++) {
            acc[m][0] += a[m] * b4.x;
            acc[m][1] += a[m] * b4.y;
            acc[m][2] += a[m] * b4.z;
            acc[m][3] += a[m] * b4.w;
        }
    }
#pragma unroll
    for (int m = 0; m < 4; m++) {
        int node = base + m0 + m;
        if (node < N_NODES) {
            float4 v = make_float4(acc[m][0], acc[m][1], acc[m][2], acc[m][3]);
            *(float4*)&out[node * 16 + nt * 4] = v;
        }
    }
}

// Load 256-node tile of g_agg into sT transposed ([feat][node]).
// Consecutive threads -> consecutive smem columns (conflict-free STS).
__device__ __forceinline__ void load_tile(float* sT, int tid, int base) {
    const float4* __restrict__ in4 = (const float4*)g_agg;
    for (int i = tid; i < TM * NQ; i += THR) {
        int m = i % TM;
        int c = i / TM;
        int node = base + m;
        float4 v = make_float4(0.f, 0.f, 0.f, 0.f);
        if (node < N_NODES) v = in4[node * NQ + c];
        sT[(4 * c + 0) * SXS + m] = v.x;
        sT[(4 * c + 1) * SXS + m] = v.y;
        sT[(4 * c + 2) * SXS + m] = v.z;
        sT[(4 * c + 3) * SXS + m] = v.w;
    }
    __syncthreads();
}

// ---------------------------------------------------------------------------
// Conv MLP: g_agg -> relu(.W1+b1) -> relu(.W2+b2) -> g_h
// grid 391 blocks @ 3 blocks/SM resident capacity 444 -> single wave.
// ---------------------------------------------------------------------------
__global__ __launch_bounds__(THR, 3) void conv_mlp_kernel(
    const float* __restrict__ W1, const float* __restrict__ b1,
    const float* __restrict__ W2, const float* __restrict__ b2) {
    __shared__ float sT[HDIM * SXS];
    int tid = threadIdx.x;
    int base = blockIdx.x * TM;
    load_tile(sT, tid, base);
    layer48_to_smem(sT, W1, b1, tid, true);
    layer48_to_gmem(sT, W2, b2, tid, base, g_h, true);
}

// ---------------------------------------------------------------------------
// Final fused kernel: conv3 MLP + fc head (4 layers), writes d_out.
// ---------------------------------------------------------------------------
__global__ __launch_bounds__(THR, 3) void final_mlp_kernel(
    const float* __restrict__ W1, const float* __restrict__ b1,
    const float* __restrict__ W2, const float* __restrict__ b2,
    const float* __restrict__ W3, const float* __restrict__ b3,
    const float* __restrict__ W4, const float* __restrict__ b4,
    float* __restrict__ out) {
    __shared__ float sT[HDIM * SXS];
    int tid = threadIdx.x;
    int base = blockIdx.x * TM;
    load_tile(sT, tid, base);
    layer48_to_smem(sT, W1, b1, tid, true);   // conv3 layer 1
    layer48_to_smem(sT, W2, b2, tid, true);   // conv3 layer 2
    layer48_to_smem(sT, W3, b3, tid, true);   // fc1 + relu
    layer16_to_gmem(sT, W4, b4, tid, base, out);  // fc2 -> out
}

// ---------------------------------------------------------------------------
extern "C" void kernel_launch(void* const* d_in, const int* in_sizes, int n_in,
                              void* d_out, int out_size) {
    const float* x   = (const float*)d_in[0];
    const int*   ei  = (const int*)d_in[1];
    const float* w11 = (const float*)d_in[2];
    const float* b11 = (const float*)d_in[3];
    const float* w12 = (const float*)d_in[4];
    const float* b12 = (const float*)d_in[5];
    const float* w21 = (const float*)d_in[6];
    const float* b21 = (const float*)d_in[7];
    const float* w22 = (const float*)d_in[8];
    const float* b22 = (const float*)d_in[9];
    const float* w31 = (const float*)d_in[10];
    const float* b31 = (const float*)d_in[11];
    const float* w32 = (const float*)d_in[12];
    const float* b32 = (const float*)d_in[13];
    const float* wf1 = (const float*)d_in[14];
    const float* bf1 = (const float*)d_in[15];
    const float* wf2 = (const float*)d_in[16];
    const float* bf2 = (const float*)d_in[17];
    float* out = (float*)d_out;

    const int TPB = 256;
    const int init_grid   = (N_NODES * NQ + TPB - 1) / TPB;
    const int build_grid  = (E_EDGES / 4 + TPB - 1) / TPB;
    const int gather_grid = (N_NODES * NQ + TPB - 1) / TPB;
    const int mlp_grid    = (N_NODES + TM - 1) / TM;   // 391

    init_kernel<<<init_grid, TPB>>>(x);
    build_kernel<<<build_grid, TPB>>>(ei);   // adjacency built ONCE, reused x3

    // Conv 1
    gather_kernel<<<gather_grid, TPB>>>();
    conv_mlp_kernel<<<mlp_grid, THR>>>(w11, b11, w12, b12);
    // Conv 2
    gather_kernel<<<gather_grid, TPB>>>();
    conv_mlp_kernel<<<mlp_grid, THR>>>(w21, b21, w22, b22);
    // Conv 3 + head fused
    gather_kernel<<<gather_grid, TPB>>>();
    final_mlp_kernel<<<mlp_grid, THR>>>(w31, b31, w32, b32,
                                        wf1, bf1, wf2, bf2, out);

    (void)in_sizes; (void)n_in; (void)out_size;
}

// round 10
// speedup vs baseline: 1.2203x; 1.0124x over previous
#include <cuda_runtime.h>
#include <cuda_fp16.h>

#define N_NODES 100000
#define E_EDGES 1600000
#define HDIM 48
#define NQ 12           // float4 columns per node (fp32 agg)
#define NH 6            // uint4 chunks per node (8 halves each) for fp16 h
#define CAP 96          // max tracked in-degree (Poisson(16): P(>50) ~ 1e-11)

#define TM 226          // logical nodes per block -> grid 443 ~= 3*148 balanced
#define TMP 256         // padded tile width (micro-tile addressing)
#define SXS 256         // shared tile stride (48*256*4 = 48KB)
#define THR 384         // 32 M-tiles (8 cols) x 12 N-tiles

// Persistent scratch (no allocations). Features between layers live in fp16
// (gather is L2-bandwidth-bound; halving bytes halves its time). All
// accumulation and MLP math stays fp32; g_agg is fp32.
__device__ __half g_h16[N_NODES * HDIM];
__device__ float  g_agg[N_NODES * HDIM];
__device__ int    g_count[N_NODES];
__device__ int    g_slots[N_NODES * CAP];

// ---------------------------------------------------------------------------
// init: h16 = fp16(x) ; count = 0
// ---------------------------------------------------------------------------
__global__ void init_kernel(const float* __restrict__ x) {
    int i = blockIdx.x * blockDim.x + threadIdx.x;
    if (i < N_NODES * HDIM / 2) {
        float2 v = ((const float2*)x)[i];
        ((__half2*)g_h16)[i] = __float22half2_rn(v);
    }
    if (i < N_NODES) g_count[i] = 0;
}

// ---------------------------------------------------------------------------
// build adjacency: bin src indices by dst. 4 edges/thread (int4 loads, MLP=4).
// ---------------------------------------------------------------------------
__global__ void build_kernel(const int* __restrict__ ei) {
    int t = blockIdx.x * blockDim.x + threadIdx.x;
    int e0 = t * 4;
    if (e0 >= E_EDGES) return;
    int4 src4 = *(const int4*)(ei + e0);
    int4 dst4 = *(const int4*)(ei + E_EDGES + e0);
    int p0 = atomicAdd(&g_count[dst4.x], 1);
    int p1 = atomicAdd(&g_count[dst4.y], 1);
    int p2 = atomicAdd(&g_count[dst4.z], 1);
    int p3 = atomicAdd(&g_count[dst4.w], 1);
    if (p0 < CAP) g_slots[dst4.x * CAP + p0] = src4.x;
    if (p1 < CAP) g_slots[dst4.y * CAP + p1] = src4.y;
    if (p2 < CAP) g_slots[dst4.z * CAP + p2] = src4.z;
    if (p3 < CAP) g_slots[dst4.w * CAP + p3] = src4.w;
}

// ---------------------------------------------------------------------------
// gather: agg[n] = h[n] + sum_{s in adj(n)} h[s], h in fp16, acc in fp32.
// One thread per (node, 8-feature chunk): uint4 = 8 halves per load.
// ---------------------------------------------------------------------------
__device__ __forceinline__ void add8(float acc[8], uint4 u) {
    float2 f0 = __half22float2(*(__half2*)&u.x);
    float2 f1 = __half22float2(*(__half2*)&u.y);
    float2 f2 = __half22float2(*(__half2*)&u.z);
    float2 f3 = __half22float2(*(__half2*)&u.w);
    acc[0] += f0.x; acc[1] += f0.y;
    acc[2] += f1.x; acc[3] += f1.y;
    acc[4] += f2.x; acc[5] += f2.y;
    acc[6] += f3.x; acc[7] += f3.y;
}

__global__ void gather_kernel() {
    int idx = blockIdx.x * blockDim.x + threadIdx.x;
    if (idx >= N_NODES * NH) return;
    int n = idx / NH;
    int c = idx % NH;

    const uint4* __restrict__ hq = (const uint4*)g_h16;
    float acc[8] = {0, 0, 0, 0, 0, 0, 0, 0};
    add8(acc, hq[n * NH + c]);                    // self (eps=0 GIN)

    int deg = min(g_count[n], CAP);
    const int* __restrict__ sl = g_slots + n * CAP;
    int i = 0;
    for (; i + 4 <= deg; i += 4) {
        int s0 = sl[i], s1 = sl[i + 1], s2 = sl[i + 2], s3 = sl[i + 3];
        uint4 v0 = hq[s0 * NH + c];
        uint4 v1 = hq[s1 * NH + c];
        uint4 v2 = hq[s2 * NH + c];
        uint4 v3 = hq[s3 * NH + c];
        add8(acc, v0); add8(acc, v1); add8(acc, v2); add8(acc, v3);
    }
    for (; i < deg; i++) {
        uint4 v = hq[sl[i] * NH + c];
        add8(acc, v);
    }
    float4* __restrict__ out4 = (float4*)g_agg;
    out4[n * NQ + c * 2 + 0] = make_float4(acc[0], acc[1], acc[2], acc[3]);
    out4[n * NQ + c * 2 + 1] = make_float4(acc[4], acc[5], acc[6], acc[7]);
}

// ---------------------------------------------------------------------------
// 48->48 layer, result back into sT (sT[feat][node], stride SXS).
// Thread (mt=tid/12, nt=tid%12) computes an 8M x 4N micro-tile:
// 32 FFMA per (2 LDS.128 + 1 LDG.128); FFMA-pipe bound.
// ---------------------------------------------------------------------------
__device__ __forceinline__ void layer48_to_smem(
    float* sT, const float* __restrict__ W, const float* __restrict__ B,
    int tid, bool relu) {
    int mt = tid / 12, nt = tid % 12;
    int m0 = mt * 8;
    const float4* __restrict__ W4 = (const float4*)W;
    float4 bias = ((const float4*)B)[nt];

    float acc[8][4];
#pragma unroll
    for (int m = 0; m < 8; m++) {
        acc[m][0] = bias.x; acc[m][1] = bias.y;
        acc[m][2] = bias.z; acc[m][3] = bias.w;
    }
#pragma unroll 8
    for (int k = 0; k < HDIM; k++) {
        float4 b4 = W4[k * NQ + nt];
        float4 a0 = *(const float4*)&sT[k * SXS + m0];
        float4 a1 = *(const float4*)&sT[k * SXS + m0 + 4];
        float a[8] = {a0.x, a0.y, a0.z, a0.w, a1.x, a1.y, a1.z, a1.w};
#pragma unroll
        for (int m = 0; m < 8; m++) {
            acc[m][0] += a[m] * b4.x;
            acc[m][1] += a[m] * b4.y;
            acc[m][2] += a[m] * b4.z;
            acc[m][3] += a[m] * b4.w;
        }
    }
    __syncthreads();   // all reads of sT complete before overwriting
#pragma unroll
    for (int n = 0; n < 4; n++) {
        float4 lo = make_float4(acc[0][n], acc[1][n], acc[2][n], acc[3][n]);
        float4 hi = make_float4(acc[4][n], acc[5][n], acc[6][n], acc[7][n]);
        if (relu) {
            lo.x = fmaxf(lo.x, 0.f); lo.y = fmaxf(lo.y, 0.f);
            lo.z = fmaxf(lo.z, 0.f); lo.w = fmaxf(lo.w, 0.f);
            hi.x = fmaxf(hi.x, 0.f); hi.y = fmaxf(hi.y, 0.f);
            hi.z = fmaxf(hi.z, 0.f); hi.w = fmaxf(hi.w, 0.f);
        }
        int row = nt * 4 + n;
        *(float4*)&sT[row * SXS + m0]     = lo;
        *(float4*)&sT[row * SXS + m0 + 4] = hi;
    }
    __syncthreads();
}

// 48 -> 48 layer writing fp16 features to g_h16 (with relu). Guarded so
// padded columns [TM, TMP) never escape (they belong to the next tile).
__device__ __forceinline__ void layer48_to_h16(
    const float* sT, const float* __restrict__ W, const float* __restrict__ B,
    int tid, int base) {
    int mt = tid / 12, nt = tid % 12;
    int m0 = mt * 8;
    const float4* __restrict__ W4 = (const float4*)W;
    float4 bias = ((const float4*)B)[nt];

    float acc[8][4];
#pragma unroll
    for (int m = 0; m < 8; m++) {
        acc[m][0] = bias.x; acc[m][1] = bias.y;
        acc[m][2] = bias.z; acc[m][3] = bias.w;
    }
#pragma unroll 8
    for (int k = 0; k < HDIM; k++) {
        float4 b4 = W4[k * NQ + nt];
        float4 a0 = *(const float4*)&sT[k * SXS + m0];
        float4 a1 = *(const float4*)&sT[k * SXS + m0 + 4];
        float a[8] = {a0.x, a0.y, a0.z, a0.w, a1.x, a1.y, a1.z, a1.w};
#pragma unroll
        for (int m = 0; m < 8; m++) {
            acc[m][0] += a[m] * b4.x;
            acc[m][1] += a[m] * b4.y;
            acc[m][2] += a[m] * b4.z;
            acc[m][3] += a[m] * b4.w;
        }
    }
#pragma unroll
    for (int m = 0; m < 8; m++) {
        int lm = m0 + m;
        int node = base + lm;
        if (lm < TM && node < N_NODES) {
            float vx = fmaxf(acc[m][0], 0.f), vy = fmaxf(acc[m][1], 0.f);
            float vz = fmaxf(acc[m][2], 0.f), vw = fmaxf(acc[m][3], 0.f);
            __half2 h0 = __float22half2_rn(make_float2(vx, vy));
            __half2 h1 = __float22half2_rn(make_float2(vz, vw));
            *(uint2*)(g_h16 + node * HDIM + nt * 4) =
                make_uint2(*(unsigned*)&h0, *(unsigned*)&h1);
        }
    }
}

// 48 -> 16 layer writing to global out[node*16 + f] (no relu).
__device__ __forceinline__ void layer16_to_gmem(
    const float* sT, const float* __restrict__ W, const float* __restrict__ B,
    int tid, int base, float* __restrict__ out) {
    int mt = tid / 4, nt = tid % 4;
    if (mt >= 64) return;                    // no barriers below this point
    int m0 = mt * 4;
    const float4* __restrict__ W4 = (const float4*)W;   // [48][4 float4 cols]
    float4 bias = ((const float4*)B)[nt];

    float acc[4][4];
#pragma unroll
    for (int m = 0; m < 4; m++) {
        acc[m][0] = bias.x; acc[m][1] = bias.y;
        acc[m][2] = bias.z; acc[m][3] = bias.w;
    }
#pragma unroll 8
    for (int k = 0; k < HDIM; k++) {
        float4 b4 = W4[k * 4 + nt];
        float4 a4 = *(const float4*)&sT[k * SXS + m0];
        float a[4] = {a4.x, a4.y, a4.z, a4.w};
#pragma unroll
        for (int m = 0; m < 4; m++) {
            acc[m][0] += a[m] * b4.x;
            acc[m][1] += a[m] * b4.y;
            acc[m][2] += a[m] * b4.z;
            acc[m][3] += a[m] * b4.w;
        }
    }
#pragma unroll
    for (int m = 0; m < 4; m++) {
        int lm = m0 + m;
        int node = base + lm;
        if (lm < TM && node < N_NODES) {
            float4 v = make_float4(acc[m][0], acc[m][1], acc[m][2], acc[m][3]);
            *(float4*)&out[node * 16 + nt * 4] = v;
        }
    }
}

// Load TM-node tile of g_agg into sT transposed ([feat][node]);
// zero-pad columns [TM, TMP).
__device__ __forceinline__ void load_tile(float* sT, int tid, int base) {
    const float4* __restrict__ in4 = (const float4*)g_agg;
    for (int i = tid; i < TMP * NQ; i += THR) {
        int m = i % TMP;
        int c = i / TMP;
        int node = base + m;
        float4 v = make_float4(0.f, 0.f, 0.f, 0.f);
        if (m < TM && node < N_NODES) v = in4[node * NQ + c];
        sT[(4 * c + 0) * SXS + m] = v.x;
        sT[(4 * c + 1) * SXS + m] = v.y;
        sT[(4 * c + 2) * SXS + m] = v.z;
        sT[(4 * c + 3) * SXS + m] = v.w;
    }
    __syncthreads();
}

// ---------------------------------------------------------------------------
// Conv MLP: g_agg -> relu(.W1+b1) -> relu(.W2+b2) -> g_h16
// grid 443 ~= 3*148 -> one balanced wave (147 SMs x 3 blocks, 1 x 2).
// ---------------------------------------------------------------------------
__global__ __launch_bounds__(THR, 3) void conv_mlp_kernel(
    const float* __restrict__ W1, const float* __restrict__ b1,
    const float* __restrict__ W2, const float* __restrict__ b2) {
    __shared__ float sT[HDIM * SXS];
    int tid = threadIdx.x;
    int base = blockIdx.x * TM;
    load_tile(sT, tid, base);
    layer48_to_smem(sT, W1, b1, tid, true);
    layer48_to_h16(sT, W2, b2, tid, base);
}

// ---------------------------------------------------------------------------
// Final fused kernel: conv3 MLP + fc head (4 layers), writes d_out.
// ---------------------------------------------------------------------------
__global__ __launch_bounds__(THR, 3) void final_mlp_kernel(
    const float* __restrict__ W1, const float* __restrict__ b1,
    const float* __restrict__ W2, const float* __restrict__ b2,
    const float* __restrict__ W3, const float* __restrict__ b3,
    const float* __restrict__ W4, const float* __restrict__ b4,
    float* __restrict__ out) {
    __shared__ float sT[HDIM * SXS];
    int tid = threadIdx.x;
    int base = blockIdx.x * TM;
    load_tile(sT, tid, base);
    layer48_to_smem(sT, W1, b1, tid, true);   // conv3 layer 1
    layer48_to_smem(sT, W2, b2, tid, true);   // conv3 layer 2
    layer48_to_smem(sT, W3, b3, tid, true);   // fc1 + relu
    layer16_to_gmem(sT, W4, b4, tid, base, out);  // fc2 -> out
}

// ---------------------------------------------------------------------------
extern "C" void kernel_launch(void* const* d_in, const int* in_sizes, int n_in,
                              void* d_out, int out_size) {
    const float* x   = (const float*)d_in[0];
    const int*   ei  = (const int*)d_in[1];
    const float* w11 = (const float*)d_in[2];
    const float* b11 = (const float*)d_in[3];
    const float* w12 = (const float*)d_in[4];
    const float* b12 = (const float*)d_in[5];
    const float* w21 = (const float*)d_in[6];
    const float* b21 = (const float*)d_in[7];
    const float* w22 = (const float*)d_in[8];
    const float* b22 = (const float*)d_in[9];
    const float* w31 = (const float*)d_in[10];
    const float* b31 = (const float*)d_in[11];
    const float* w32 = (const float*)d_in[12];
    const float* b32 = (const float*)d_in[13];
    const float* wf1 = (const float*)d_in[14];
    const float* bf1 = (const float*)d_in[15];
    const float* wf2 = (const float*)d_in[16];
    const float* bf2 = (const float*)d_in[17];
    float* out = (float*)d_out;

    const int TPB = 256;
    const int init_grid   = (N_NODES * HDIM / 2 + TPB - 1) / TPB;
    const int build_grid  = (E_EDGES / 4 + TPB - 1) / TPB;
    const int gather_grid = (N_NODES * NH + TPB - 1) / TPB;
    const int mlp_grid    = (N_NODES + TM - 1) / TM;   // 443

    init_kernel<<<init_grid, TPB>>>(x);
    build_kernel<<<build_grid, TPB>>>(ei);   // adjacency built ONCE, reused x3

    // Conv 1
    gather_kernel<<<gather_grid, TPB>>>();
    conv_mlp_kernel<<<mlp_grid, THR>>>(w11, b11, w12, b12);
    // Conv 2
    gather_kernel<<<gather_grid, TPB>>>();
    conv_mlp_kernel<<<mlp_grid, THR>>>(w21, b21, w22, b22);
    // Conv 3 + head fused
    gather_kernel<<<gather_grid, TPB>>>();
    final_mlp_kernel<<<mlp_grid, THR>>>(w31, b31, w32, b32,
                                        wf1, bf1, wf2, bf2, out);

    (void)in_sizes; (void)n_in; (void)out_size;
}

// round 11
// speedup vs baseline: 1.2427x; 1.0184x over previous
#include <cuda_runtime.h>
#include <cuda_fp16.h>

#define N_NODES 100000
#define E_EDGES 1600000
#define HDIM 48
#define NQ 12           // float4 columns per node (fp32 agg)
#define NH 6            // uint4 chunks per node (8 halves each) for fp16 h
#define CAP 96          // max tracked in-degree (Poisson(16): P(>50) ~ 1e-11)

#define TM 226          // logical nodes per block -> grid 443 ~= 3*148 balanced
#define TMP 256         // padded tile width (micro-tile addressing)
#define SXS 256         // shared tile stride (48*256*4 = 48KB)
#define THR 384         // 32 M-tiles (8 cols) x 12 N-tiles

typedef unsigned long long ull;

// ---- packed f32x2 helpers (FFMA2: 2 fp32 FMA per instruction, exact fp32) ----
__device__ __forceinline__ ull pack2(float lo, float hi) {
    ull r;
    asm("mov.b64 %0, {%1, %2};" : "=l"(r) : "f"(lo), "f"(hi));
    return r;
}
__device__ __forceinline__ float2 unpack2(ull v) {
    float2 f;
    asm("mov.b64 {%0, %1}, %2;" : "=f"(f.x), "=f"(f.y) : "l"(v));
    return f;
}
__device__ __forceinline__ ull fma2(ull a, ull b, ull c) {
    ull d;
    asm("fma.rn.f32x2 %0, %1, %2, %3;" : "=l"(d) : "l"(a), "l"(b), "l"(c));
    return d;
}

// Persistent scratch (no allocations). Features between layers live in fp16;
// all accumulation and MLP math stays fp32; g_agg is fp32.
__device__ __half g_h16[N_NODES * HDIM];
__device__ float  g_agg[N_NODES * HDIM];
__device__ int    g_count[N_NODES];
__device__ int    g_slots[N_NODES * CAP];

// ---------------------------------------------------------------------------
// init: h16 = fp16(x) ; count = 0
// ---------------------------------------------------------------------------
__global__ void init_kernel(const float* __restrict__ x) {
    int i = blockIdx.x * blockDim.x + threadIdx.x;
    if (i < N_NODES * HDIM / 2) {
        float2 v = ((const float2*)x)[i];
        ((__half2*)g_h16)[i] = __float22half2_rn(v);
    }
    if (i < N_NODES) g_count[i] = 0;
}

// ---------------------------------------------------------------------------
// build adjacency: bin src indices by dst. 4 edges/thread (int4 loads, MLP=4).
// ---------------------------------------------------------------------------
__global__ void build_kernel(const int* __restrict__ ei) {
    int t = blockIdx.x * blockDim.x + threadIdx.x;
    int e0 = t * 4;
    if (e0 >= E_EDGES) return;
    int4 src4 = *(const int4*)(ei + e0);
    int4 dst4 = *(const int4*)(ei + E_EDGES + e0);
    int p0 = atomicAdd(&g_count[dst4.x], 1);
    int p1 = atomicAdd(&g_count[dst4.y], 1);
    int p2 = atomicAdd(&g_count[dst4.z], 1);
    int p3 = atomicAdd(&g_count[dst4.w], 1);
    if (p0 < CAP) g_slots[dst4.x * CAP + p0] = src4.x;
    if (p1 < CAP) g_slots[dst4.y * CAP + p1] = src4.y;
    if (p2 < CAP) g_slots[dst4.z * CAP + p2] = src4.z;
    if (p3 < CAP) g_slots[dst4.w * CAP + p3] = src4.w;
}

// ---------------------------------------------------------------------------
// gather: agg[n] = h[n] + sum_{s in adj(n)} h[s], h in fp16, acc in fp32.
// ---------------------------------------------------------------------------
__device__ __forceinline__ void add8(float acc[8], uint4 u) {
    float2 f0 = __half22float2(*(__half2*)&u.x);
    float2 f1 = __half22float2(*(__half2*)&u.y);
    float2 f2 = __half22float2(*(__half2*)&u.z);
    float2 f3 = __half22float2(*(__half2*)&u.w);
    acc[0] += f0.x; acc[1] += f0.y;
    acc[2] += f1.x; acc[3] += f1.y;
    acc[4] += f2.x; acc[5] += f2.y;
    acc[6] += f3.x; acc[7] += f3.y;
}

__global__ void gather_kernel() {
    int idx = blockIdx.x * blockDim.x + threadIdx.x;
    if (idx >= N_NODES * NH) return;
    int n = idx / NH;
    int c = idx % NH;

    const uint4* __restrict__ hq = (const uint4*)g_h16;
    float acc[8] = {0, 0, 0, 0, 0, 0, 0, 0};
    add8(acc, hq[n * NH + c]);                    // self (eps=0 GIN)

    int deg = min(g_count[n], CAP);
    const int* __restrict__ sl = g_slots + n * CAP;
    int i = 0;
    for (; i + 4 <= deg; i += 4) {
        int s0 = sl[i], s1 = sl[i + 1], s2 = sl[i + 2], s3 = sl[i + 3];
        uint4 v0 = hq[s0 * NH + c];
        uint4 v1 = hq[s1 * NH + c];
        uint4 v2 = hq[s2 * NH + c];
        uint4 v3 = hq[s3 * NH + c];
        add8(acc, v0); add8(acc, v1); add8(acc, v2); add8(acc, v3);
    }
    for (; i < deg; i++) {
        uint4 v = hq[sl[i] * NH + c];
        add8(acc, v);
    }
    float4* __restrict__ out4 = (float4*)g_agg;
    out4[n * NQ + c * 2 + 0] = make_float4(acc[0], acc[1], acc[2], acc[3]);
    out4[n * NQ + c * 2 + 1] = make_float4(acc[4], acc[5], acc[6], acc[7]);
}

// ---------------------------------------------------------------------------
// 48->48 layer via FFMA2. Thread (mt=tid/12, nt=tid%12), 8M x 4N micro-tile
// as 4 node-pairs x 4 N. LDS.128 delivers (f32,f32) pairs directly; only B
// needs a 4x mov.b64 splat per k. 16 fma.rn.f32x2 per k (was 32 FFMA).
// ---------------------------------------------------------------------------
__device__ __forceinline__ void layer48_to_smem(
    float* sT, const float* __restrict__ W, const float* __restrict__ B,
    int tid, bool relu) {
    int mt = tid / 12, nt = tid % 12;
    int m0 = mt * 8;
    const float4* __restrict__ W4 = (const float4*)W;
    float4 bias = ((const float4*)B)[nt];

    ull acc2[4][4];
    {
        ull b0 = pack2(bias.x, bias.x), b1 = pack2(bias.y, bias.y);
        ull b2 = pack2(bias.z, bias.z), b3 = pack2(bias.w, bias.w);
#pragma unroll
        for (int p = 0; p < 4; p++) {
            acc2[p][0] = b0; acc2[p][1] = b1; acc2[p][2] = b2; acc2[p][3] = b3;
        }
    }
#pragma unroll 8
    for (int k = 0; k < HDIM; k++) {
        float4 b4 = W4[k * NQ + nt];
        ull bb[4] = {pack2(b4.x, b4.x), pack2(b4.y, b4.y),
                     pack2(b4.z, b4.z), pack2(b4.w, b4.w)};
        ulonglong2 A0 = *(const ulonglong2*)&sT[k * SXS + m0];
        ulonglong2 A1 = *(const ulonglong2*)&sT[k * SXS + m0 + 4];
        ull ap[4] = {A0.x, A0.y, A1.x, A1.y};
#pragma unroll
        for (int p = 0; p < 4; p++) {
#pragma unroll
            for (int n = 0; n < 4; n++)
                acc2[p][n] = fma2(ap[p], bb[n], acc2[p][n]);
        }
    }
    __syncthreads();   // all reads of sT complete before overwriting
#pragma unroll
    for (int n = 0; n < 4; n++) {
        float2 u0 = unpack2(acc2[0][n]), u1 = unpack2(acc2[1][n]);
        float2 u2 = unpack2(acc2[2][n]), u3 = unpack2(acc2[3][n]);
        float4 lo = make_float4(u0.x, u0.y, u1.x, u1.y);
        float4 hi = make_float4(u2.x, u2.y, u3.x, u3.y);
        if (relu) {
            lo.x = fmaxf(lo.x, 0.f); lo.y = fmaxf(lo.y, 0.f);
            lo.z = fmaxf(lo.z, 0.f); lo.w = fmaxf(lo.w, 0.f);
            hi.x = fmaxf(hi.x, 0.f); hi.y = fmaxf(hi.y, 0.f);
            hi.z = fmaxf(hi.z, 0.f); hi.w = fmaxf(hi.w, 0.f);
        }
        int row = nt * 4 + n;
        *(float4*)&sT[row * SXS + m0]     = lo;
        *(float4*)&sT[row * SXS + m0 + 4] = hi;
    }
    __syncthreads();
}

// 48 -> 48 layer (FFMA2) writing fp16 features to g_h16 (with relu).
__device__ __forceinline__ void layer48_to_h16(
    const float* sT, const float* __restrict__ W, const float* __restrict__ B,
    int tid, int base) {
    int mt = tid / 12, nt = tid % 12;
    int m0 = mt * 8;
    const float4* __restrict__ W4 = (const float4*)W;
    float4 bias = ((const float4*)B)[nt];

    ull acc2[4][4];
    {
        ull b0 = pack2(bias.x, bias.x), b1 = pack2(bias.y, bias.y);
        ull b2 = pack2(bias.z, bias.z), b3 = pack2(bias.w, bias.w);
#pragma unroll
        for (int p = 0; p < 4; p++) {
            acc2[p][0] = b0; acc2[p][1] = b1; acc2[p][2] = b2; acc2[p][3] = b3;
        }
    }
#pragma unroll 8
    for (int k = 0; k < HDIM; k++) {
        float4 b4 = W4[k * NQ + nt];
        ull bb[4] = {pack2(b4.x, b4.x), pack2(b4.y, b4.y),
                     pack2(b4.z, b4.z), pack2(b4.w, b4.w)};
        ulonglong2 A0 = *(const ulonglong2*)&sT[k * SXS + m0];
        ulonglong2 A1 = *(const ulonglong2*)&sT[k * SXS + m0 + 4];
        ull ap[4] = {A0.x, A0.y, A1.x, A1.y};
#pragma unroll
        for (int p = 0; p < 4; p++) {
#pragma unroll
            for (int n = 0; n < 4; n++)
                acc2[p][n] = fma2(ap[p], bb[n], acc2[p][n]);
        }
    }
    // acc2[p][n]: nodes (m0+2p, m0+2p+1), feature nt*4+n
#pragma unroll
    for (int p = 0; p < 4; p++) {
        float2 v0 = unpack2(acc2[p][0]);
        float2 v1 = unpack2(acc2[p][1]);
        float2 v2 = unpack2(acc2[p][2]);
        float2 v3 = unpack2(acc2[p][3]);
        // node lm = m0+2p (lo halves) and m0+2p+1 (hi halves)
#pragma unroll
        for (int h = 0; h < 2; h++) {
            int lm = m0 + 2 * p + h;
            int node = base + lm;
            if (lm < TM && node < N_NODES) {
                float vx = h ? v0.y : v0.x;
                float vy = h ? v1.y : v1.x;
                float vz = h ? v2.y : v2.x;
                float vw = h ? v3.y : v3.x;
                vx = fmaxf(vx, 0.f); vy = fmaxf(vy, 0.f);
                vz = fmaxf(vz, 0.f); vw = fmaxf(vw, 0.f);
                __half2 h0 = __float22half2_rn(make_float2(vx, vy));
                __half2 h1 = __float22half2_rn(make_float2(vz, vw));
                *(uint2*)(g_h16 + node * HDIM + nt * 4) =
                    make_uint2(*(unsigned*)&h0, *(unsigned*)&h1);
            }
        }
    }
}

// 48 -> 16 layer (FFMA2) writing to out[node*16 + f] (no relu).
__device__ __forceinline__ void layer16_to_gmem(
    const float* sT, const float* __restrict__ W, const float* __restrict__ B,
    int tid, int base, float* __restrict__ out) {
    int mt = tid / 4, nt = tid % 4;
    if (mt >= 64) return;                    // no barriers below this point
    int m0 = mt * 4;
    const float4* __restrict__ W4 = (const float4*)W;   // [48][4 float4 cols]
    float4 bias = ((const float4*)B)[nt];

    ull acc2[2][4];
    {
        ull b0 = pack2(bias.x, bias.x), b1 = pack2(bias.y, bias.y);
        ull b2 = pack2(bias.z, bias.z), b3 = pack2(bias.w, bias.w);
#pragma unroll
        for (int p = 0; p < 2; p++) {
            acc2[p][0] = b0; acc2[p][1] = b1; acc2[p][2] = b2; acc2[p][3] = b3;
        }
    }
#pragma unroll 8
    for (int k = 0; k < HDIM; k++) {
        float4 b4 = W4[k * 4 + nt];
        ull bb[4] = {pack2(b4.x, b4.x), pack2(b4.y, b4.y),
                     pack2(b4.z, b4.z), pack2(b4.w, b4.w)};
        ulonglong2 A0 = *(const ulonglong2*)&sT[k * SXS + m0];
        ull ap[2] = {A0.x, A0.y};
#pragma unroll
        for (int p = 0; p < 2; p++) {
#pragma unroll
            for (int n = 0; n < 4; n++)
                acc2[p][n] = fma2(ap[p], bb[n], acc2[p][n]);
        }
    }
#pragma unroll
    for (int p = 0; p < 2; p++) {
        float2 v0 = unpack2(acc2[p][0]);
        float2 v1 = unpack2(acc2[p][1]);
        float2 v2 = unpack2(acc2[p][2]);
        float2 v3 = unpack2(acc2[p][3]);
#pragma unroll
        for (int h = 0; h < 2; h++) {
            int lm = m0 + 2 * p + h;
            int node = base + lm;
            if (lm < TM && node < N_NODES) {
                float4 v = make_float4(h ? v0.y : v0.x, h ? v1.y : v1.x,
                                       h ? v2.y : v2.x, h ? v3.y : v3.x);
                *(float4*)&out[node * 16 + nt * 4] = v;
            }
        }
    }
}

// Load TM-node tile of g_agg into sT transposed ([feat][node]);
// zero-pad columns [TM, TMP).
__device__ __forceinline__ void load_tile(float* sT, int tid, int base) {
    const float4* __restrict__ in4 = (const float4*)g_agg;
    for (int i = tid; i < TMP * NQ; i += THR) {
        int m = i % TMP;
        int c = i / TMP;
        int node = base + m;
        float4 v = make_float4(0.f, 0.f, 0.f, 0.f);
        if (m < TM && node < N_NODES) v = in4[node * NQ + c];
        sT[(4 * c + 0) * SXS + m] = v.x;
        sT[(4 * c + 1) * SXS + m] = v.y;
        sT[(4 * c + 2) * SXS + m] = v.z;
        sT[(4 * c + 3) * SXS + m] = v.w;
    }
    __syncthreads();
}

// ---------------------------------------------------------------------------
// Conv MLP: g_agg -> relu(.W1+b1) -> relu(.W2+b2) -> g_h16
// grid 443 ~= 3*148 -> one balanced wave.
// ---------------------------------------------------------------------------
__global__ __launch_bounds__(THR, 3) void conv_mlp_kernel(
    const float* __restrict__ W1, const float* __restrict__ b1,
    const float* __restrict__ W2, const float* __restrict__ b2) {
    __shared__ float sT[HDIM * SXS];
    int tid = threadIdx.x;
    int base = blockIdx.x * TM;
    load_tile(sT, tid, base);
    layer48_to_smem(sT, W1, b1, tid, true);
    layer48_to_h16(sT, W2, b2, tid, base);
}

// ---------------------------------------------------------------------------
// Final fused kernel: conv3 MLP + fc head (4 layers), writes d_out.
// ---------------------------------------------------------------------------
__global__ __launch_bounds__(THR, 3) void final_mlp_kernel(
    const float* __restrict__ W1, const float* __restrict__ b1,
    const float* __restrict__ W2, const float* __restrict__ b2,
    const float* __restrict__ W3, const float* __restrict__ b3,
    const float* __restrict__ W4, const float* __restrict__ b4,
    float* __restrict__ out) {
    __shared__ float sT[HDIM * SXS];
    int tid = threadIdx.x;
    int base = blockIdx.x * TM;
    load_tile(sT, tid, base);
    layer48_to_smem(sT, W1, b1, tid, true);   // conv3 layer 1
    layer48_to_smem(sT, W2, b2, tid, true);   // conv3 layer 2
    layer48_to_smem(sT, W3, b3, tid, true);   // fc1 + relu
    layer16_to_gmem(sT, W4, b4, tid, base, out);  // fc2 -> out
}

// ---------------------------------------------------------------------------
extern "C" void kernel_launch(void* const* d_in, const int* in_sizes, int n_in,
                              void* d_out, int out_size) {
    const float* x   = (const float*)d_in[0];
    const int*   ei  = (const int*)d_in[1];
    const float* w11 = (const float*)d_in[2];
    const float* b11 = (const float*)d_in[3];
    const float* w12 = (const float*)d_in[4];
    const float* b12 = (const float*)d_in[5];
    const float* w21 = (const float*)d_in[6];
    const float* b21 = (const float*)d_in[7];
    const float* w22 = (const float*)d_in[8];
    const float* b22 = (const float*)d_in[9];
    const float* w31 = (const float*)d_in[10];
    const float* b31 = (const float*)d_in[11];
    const float* w32 = (const float*)d_in[12];
    const float* b32 = (const float*)d_in[13];
    const float* wf1 = (const float*)d_in[14];
    const float* bf1 = (const float*)d_in[15];
    const float* wf2 = (const float*)d_in[16];
    const float* bf2 = (const float*)d_in[17];
    float* out = (float*)d_out;

    const int TPB = 256;
    const int init_grid   = (N_NODES * HDIM / 2 + TPB - 1) / TPB;
    const int build_grid  = (E_EDGES / 4 + TPB - 1) / TPB;
    const int gather_grid = (N_NODES * NH + TPB - 1) / TPB;
    const int mlp_grid    = (N_NODES + TM - 1) / TM;   // 443

    init_kernel<<<init_grid, TPB>>>(x);
    build_kernel<<<build_grid, TPB>>>(ei);   // adjacency built ONCE, reused x3

    // Conv 1
    gather_kernel<<<gather_grid, TPB>>>();
    conv_mlp_kernel<<<mlp_grid, THR>>>(w11, b11, w12, b12);
    // Conv 2
    gather_kernel<<<gather_grid, TPB>>>();
    conv_mlp_kernel<<<mlp_grid, THR>>>(w21, b21, w22, b22);
    // Conv 3 + head fused
    gather_kernel<<<gather_grid, TPB>>>();
    final_mlp_kernel<<<mlp_grid, THR>>>(w31, b31, w32, b32,
                                        wf1, bf1, wf2, bf2, out);

    (void)in_sizes; (void)n_in; (void)out_size;
}

// round 16
// speedup vs baseline: 1.9076x; 1.5351x over previous
#include <cuda_runtime.h>
#include <cuda_fp16.h>
#include <mma.h>
using namespace nvcuda;

#define N_NODES 100000
#define E_EDGES 1600000
#define HDIM 48
#define NH 6            // uint4 (8-half) chunks per node row
#define CAP 96          // max tracked in-degree (Poisson(16): P(>50) ~ 1e-11)

#define TM 226          // nodes per block -> grid 443 ~= 3*148, single wave
#define SWH 56          // smem row stride in halves (112B)
#define THR 256         // 8 warps x 32 rows each

// Persistent scratch (no allocations). Node features fp16; MMA accum fp32.
__device__ __align__(16) __half g_h16[N_NODES * HDIM];    // current features
__device__ __align__(16) __half g_agg16[N_NODES * HDIM];  // self+neighbor sum
__device__ int g_count[N_NODES];
__device__ int g_slots[N_NODES * CAP];
// Plain fp16 row-major weight copies (wmma loads them directly; no custom
// fragment packing). 7x 48x48 (w11,w12,w21,w22,w31,w32,wf1) + 48x16 (wf2).
__device__ __align__(16) __half g_w48[7 * 48 * 48];
__device__ __align__(16) __half g_wf2[48 * 16];

// ---------------------------------------------------------------------------
// init: h16 = fp16(x) ; count = 0
// ---------------------------------------------------------------------------
__global__ void init_kernel(const float* __restrict__ x) {
    int i = blockIdx.x * blockDim.x + threadIdx.x;
    if (i < N_NODES * HDIM / 2) {
        float2 v = ((const float2*)x)[i];
        ((__half2*)g_h16)[i] = __float22half2_rn(v);
    }
    if (i < N_NODES) g_count[i] = 0;
}

// ---------------------------------------------------------------------------
// prep: elementwise fp32 -> fp16 copy of all weight matrices (row-major).
// ---------------------------------------------------------------------------
__global__ void prep_kernel(
    const float* w11, const float* w12, const float* w21, const float* w22,
    const float* w31, const float* w32, const float* wf1, const float* wf2) {
    int e = blockIdx.x * blockDim.x + threadIdx.x;
    if (e < 7 * 2304) {
        const float* ws[7] = {w11, w12, w21, w22, w31, w32, wf1};
        g_w48[e] = __float2half(ws[e / 2304][e % 2304]);
    } else if (e < 7 * 2304 + 768) {
        g_wf2[e - 7 * 2304] = __float2half(wf2[e - 7 * 2304]);
    }
}

// ---------------------------------------------------------------------------
// build adjacency: bin src indices by dst. 4 edges/thread (int4 loads, MLP=4).
// ---------------------------------------------------------------------------
__global__ void build_kernel(const int* __restrict__ ei) {
    int t = blockIdx.x * blockDim.x + threadIdx.x;
    int e0 = t * 4;
    if (e0 >= E_EDGES) return;
    int4 src4 = *(const int4*)(ei + e0);
    int4 dst4 = *(const int4*)(ei + E_EDGES + e0);
    int p0 = atomicAdd(&g_count[dst4.x], 1);
    int p1 = atomicAdd(&g_count[dst4.y], 1);
    int p2 = atomicAdd(&g_count[dst4.z], 1);
    int p3 = atomicAdd(&g_count[dst4.w], 1);
    if (p0 < CAP) g_slots[dst4.x * CAP + p0] = src4.x;
    if (p1 < CAP) g_slots[dst4.y * CAP + p1] = src4.y;
    if (p2 < CAP) g_slots[dst4.z * CAP + p2] = src4.z;
    if (p3 < CAP) g_slots[dst4.w * CAP + p3] = src4.w;
}

// ---------------------------------------------------------------------------
// gather: agg16[n] = fp16( h[n] + sum_{s in adj(n)} h[s] ), acc fp32.
// ---------------------------------------------------------------------------
__device__ __forceinline__ void add8(float acc[8], uint4 u) {
    float2 f0 = __half22float2(*(__half2*)&u.x);
    float2 f1 = __half22float2(*(__half2*)&u.y);
    float2 f2 = __half22float2(*(__half2*)&u.z);
    float2 f3 = __half22float2(*(__half2*)&u.w);
    acc[0] += f0.x; acc[1] += f0.y;
    acc[2] += f1.x; acc[3] += f1.y;
    acc[4] += f2.x; acc[5] += f2.y;
    acc[6] += f3.x; acc[7] += f3.y;
}

__global__ void gather_kernel() {
    int idx = blockIdx.x * blockDim.x + threadIdx.x;
    if (idx >= N_NODES * NH) return;
    int n = idx / NH;
    int c = idx % NH;

    const uint4* __restrict__ hq = (const uint4*)g_h16;
    float acc[8] = {0, 0, 0, 0, 0, 0, 0, 0};
    add8(acc, hq[n * NH + c]);                    // self (eps=0 GIN)

    int deg = min(g_count[n], CAP);
    const int* __restrict__ sl = g_slots + n * CAP;
    int i = 0;
    for (; i + 4 <= deg; i += 4) {
        int s0 = sl[i], s1 = sl[i + 1], s2 = sl[i + 2], s3 = sl[i + 3];
        uint4 v0 = hq[s0 * NH + c];
        uint4 v1 = hq[s1 * NH + c];
        uint4 v2 = hq[s2 * NH + c];
        uint4 v3 = hq[s3 * NH + c];
        add8(acc, v0); add8(acc, v1); add8(acc, v2); add8(acc, v3);
    }
    for (; i < deg; i++) {
        uint4 v = hq[sl[i] * NH + c];
        add8(acc, v);
    }
    __half2 p0 = __floats2half2_rn(acc[0], acc[1]);
    __half2 p1 = __floats2half2_rn(acc[2], acc[3]);
    __half2 p2 = __floats2half2_rn(acc[4], acc[5]);
    __half2 p3 = __floats2half2_rn(acc[6], acc[7]);
    ((uint4*)g_agg16)[n * NH + c] = make_uint4(
        *(unsigned*)&p0, *(unsigned*)&p1, *(unsigned*)&p2, *(unsigned*)&p3);
}

// ---------------------------------------------------------------------------
// wmma MLP blocks. Smem tile sA: row-major fp16 [256][48], row stride SWH=56
// halves (112B). Warp w owns rows [w*32, w*32+32) -> no cross-warp data flow,
// __syncwarp only. Epilogue: per-warp 16x16 fp32 scratch (1KB).
// ---------------------------------------------------------------------------
template <bool TO_SMEM>
__device__ __forceinline__ void layer48_wmma(
    __half* sA, float* scr_w, const __half* __restrict__ W,
    const float* __restrict__ B, int w, int lane, int base) {
    wmma::fragment<wmma::accumulator, 16, 16, 16, float> c[2][3];
#pragma unroll
    for (int mt = 0; mt < 2; mt++)
#pragma unroll
        for (int nc = 0; nc < 3; nc++) wmma::fill_fragment(c[mt][nc], 0.f);

#pragma unroll
    for (int kc = 0; kc < 3; kc++) {
        wmma::fragment<wmma::matrix_a, 16, 16, 16, __half, wmma::row_major> a0, a1;
        wmma::load_matrix_sync(a0, sA + (w * 32) * SWH + kc * 16, SWH);
        wmma::load_matrix_sync(a1, sA + (w * 32 + 16) * SWH + kc * 16, SWH);
#pragma unroll
        for (int nc = 0; nc < 3; nc++) {
            wmma::fragment<wmma::matrix_b, 16, 16, 16, __half, wmma::row_major> b;
            wmma::load_matrix_sync(b, W + kc * 16 * 48 + nc * 16, 48);
            wmma::mma_sync(c[0][nc], a0, b, c[0][nc]);
            wmma::mma_sync(c[1][nc], a1, b, c[1][nc]);
        }
    }
    __syncwarp();   // all sA reads complete before epilogue overwrites
#pragma unroll
    for (int mt = 0; mt < 2; mt++) {
#pragma unroll
        for (int nc = 0; nc < 3; nc++) {
            wmma::store_matrix_sync(scr_w, c[mt][nc], 16, wmma::mem_row_major);
            __syncwarp();
#pragma unroll
            for (int j = 0; j < 8; j++) {
                int elem = j * 32 + lane;       // 16x16 = 256 elems
                int r = elem >> 4, col = nc * 16 + (elem & 15);
                float v = fmaxf(scr_w[elem] + B[col], 0.f);
                if (TO_SMEM) {
                    sA[(w * 32 + mt * 16 + r) * SWH + col] = __float2half(v);
                } else {
                    int lm = w * 32 + mt * 16 + r;
                    int node = base + lm;
                    if (lm < TM && node < N_NODES)
                        g_h16[node * HDIM + col] = __float2half(v);
                }
            }
            __syncwarp();
        }
    }
}

// fc2: 48 -> 16, no relu, fp32 out (guarded).
__device__ __forceinline__ void layer16_wmma(
    const __half* sA, float* scr_w, const float* __restrict__ B,
    int w, int lane, int base, float* __restrict__ out) {
    wmma::fragment<wmma::accumulator, 16, 16, 16, float> c[2];
    wmma::fill_fragment(c[0], 0.f);
    wmma::fill_fragment(c[1], 0.f);
#pragma unroll
    for (int kc = 0; kc < 3; kc++) {
        wmma::fragment<wmma::matrix_a, 16, 16, 16, __half, wmma::row_major> a0, a1;
        wmma::load_matrix_sync(a0, sA + (w * 32) * SWH + kc * 16, SWH);
        wmma::load_matrix_sync(a1, sA + (w * 32 + 16) * SWH + kc * 16, SWH);
        wmma::fragment<wmma::matrix_b, 16, 16, 16, __half, wmma::row_major> b;
        wmma::load_matrix_sync(b, g_wf2 + kc * 16 * 16, 16);
        wmma::mma_sync(c[0], a0, b, c[0]);
        wmma::mma_sync(c[1], a1, b, c[1]);
    }
#pragma unroll
    for (int mt = 0; mt < 2; mt++) {
        wmma::store_matrix_sync(scr_w, c[mt], 16, wmma::mem_row_major);
        __syncwarp();
#pragma unroll
        for (int j = 0; j < 8; j++) {
            int elem = j * 32 + lane;
            int r = elem >> 4, col = elem & 15;
            int lm = w * 32 + mt * 16 + r;
            int node = base + lm;
            if (lm < TM && node < N_NODES)
                out[node * 16 + col] = scr_w[elem] + B[col];
        }
        __syncwarp();
    }
}

// Warp w loads its own 32 rows of the tile from g_agg16 (zero-pad OOB).
__device__ __forceinline__ void load_tile(__half* sA, int w, int lane, int base) {
    const uint4* __restrict__ src = (const uint4*)g_agg16;
#pragma unroll
    for (int i = 0; i < 6; i++) {
        int item = i * 32 + lane;            // 192 items = 32 rows x 6 chunks
        int r = w * 32 + item / 6;
        int c = item % 6;
        int node = base + r;
        uint4 v = make_uint4(0, 0, 0, 0);
        if (r < TM && node < N_NODES) v = src[node * NH + c];
        *(uint4*)&sA[r * SWH + c * 8] = v;
    }
    __syncwarp();
}

// ---------------------------------------------------------------------------
// Conv MLP (wmma): agg16 -> relu(W1) -> relu(W2) -> g_h16
// smem 36KB -> 3 blocks/SM, grid 443 -> single wave.
// ---------------------------------------------------------------------------
__global__ __launch_bounds__(THR, 3) void conv_mma_kernel(
    int wi1, int wi2, const float* __restrict__ b1, const float* __restrict__ b2) {
    __shared__ __align__(32) __half sA[256 * SWH];
    __shared__ __align__(32) float scr[8 * 256];
    int tid = threadIdx.x, w = tid >> 5, lane = tid & 31;
    int base = blockIdx.x * TM;
    float* scr_w = scr + w * 256;
    load_tile(sA, w, lane, base);
    layer48_wmma<true>(sA, scr_w, g_w48 + wi1 * 2304, b1, w, lane, base);
    layer48_wmma<false>(sA, scr_w, g_w48 + wi2 * 2304, b2, w, lane, base);
}

// ---------------------------------------------------------------------------
// Final (wmma): conv3 L1,L2 + fc1 (relu) + fc2 -> d_out.
// ---------------------------------------------------------------------------
__global__ __launch_bounds__(THR, 3) void final_mma_kernel(
    const float* __restrict__ b1, const float* __restrict__ b2,
    const float* __restrict__ b3, const float* __restrict__ b4,
    float* __restrict__ out) {
    __shared__ __align__(32) __half sA[256 * SWH];
    __shared__ __align__(32) float scr[8 * 256];
    int tid = threadIdx.x, w = tid >> 5, lane = tid & 31;
    int base = blockIdx.x * TM;
    float* scr_w = scr + w * 256;
    load_tile(sA, w, lane, base);
    layer48_wmma<true>(sA, scr_w, g_w48 + 4 * 2304, b1, w, lane, base);  // w31
    layer48_wmma<true>(sA, scr_w, g_w48 + 5 * 2304, b2, w, lane, base);  // w32
    layer48_wmma<true>(sA, scr_w, g_w48 + 6 * 2304, b3, w, lane, base);  // wf1
    layer16_wmma(sA, scr_w, b4, w, lane, base, out);                     // wf2
}

// ---------------------------------------------------------------------------
extern "C" void kernel_launch(void* const* d_in, const int* in_sizes, int n_in,
                              void* d_out, int out_size) {
    const float* x   = (const float*)d_in[0];
    const int*   ei  = (const int*)d_in[1];
    const float* w11 = (const float*)d_in[2];
    const float* b11 = (const float*)d_in[3];
    const float* w12 = (const float*)d_in[4];
    const float* b12 = (const float*)d_in[5];
    const float* w21 = (const float*)d_in[6];
    const float* b21 = (const float*)d_in[7];
    const float* w22 = (const float*)d_in[8];
    const float* b22 = (const float*)d_in[9];
    const float* w31 = (const float*)d_in[10];
    const float* b31 = (const float*)d_in[11];
    const float* w32 = (const float*)d_in[12];
    const float* b32 = (const float*)d_in[13];
    const float* wf1 = (const float*)d_in[14];
    const float* bf1 = (const float*)d_in[15];
    const float* wf2 = (const float*)d_in[16];
    const float* bf2 = (const float*)d_in[17];
    float* out = (float*)d_out;

    const int TPB = 256;
    const int init_grid   = (N_NODES * HDIM / 2 + TPB - 1) / TPB;
    const int prep_grid   = (7 * 2304 + 768 + TPB - 1) / TPB;
    const int build_grid  = (E_EDGES / 4 + TPB - 1) / TPB;
    const int gather_grid = (N_NODES * NH + TPB - 1) / TPB;
    const int mlp_grid    = (N_NODES + TM - 1) / TM;   // 443

    init_kernel<<<init_grid, TPB>>>(x);
    prep_kernel<<<prep_grid, TPB>>>(w11, w12, w21, w22, w31, w32, wf1, wf2);
    build_kernel<<<build_grid, TPB>>>(ei);   // adjacency built ONCE, reused x3

    // Conv 1
    gather_kernel<<<gather_grid, TPB>>>();
    conv_mma_kernel<<<mlp_grid, THR>>>(0, 1, b11, b12);
    // Conv 2
    gather_kernel<<<gather_grid, TPB>>>();
    conv_mma_kernel<<<mlp_grid, THR>>>(2, 3, b21, b22);
    // Conv 3 + head fused
    gather_kernel<<<gather_grid, TPB>>>();
    final_mma_kernel<<<mlp_grid, THR>>>(b31, b32, bf1, bf2, out);

    (void)in_sizes; (void)n_in; (void)out_size;
}